// round 1
// baseline (speedup 1.0000x reference)
#include <cuda_runtime.h>

// Problem constants
#define Bn 16
#define Cn 512
#define Hn 80
#define Wn 80
#define HWn (Hn*Wn)          // 6400
#define CHWn (Cn*HWn)        // 3276800
#define TOTALn (Bn*CHWn)     // 52428800
#define NPIX (Bn*HWn)        // 102400

#define K1_CHUNK 64
#define K1_NCHUNK (Cn/K1_CHUNK)   // 8

#define K2_TPB 256
#define K2_EPB (K2_TPB*4)         // 1024 elements per block
#define NBLK2 (TOTALn/K2_EPB)     // 51200
#define CAP 64                    // max detections recorded per K2 block

// ---- scratch (allocation-free: __device__ globals) ----
__device__ unsigned int g_m[NPIX];             // depthwise max as uint bits (relu >= 0)
__device__ unsigned int g_counts[NBLK2];
__device__ unsigned int g_offsets[NBLK2];
__device__ unsigned int g_scratch[NBLK2 * CAP]; // packed (h<<8)|w per detection

// K0: init output padding and zero g_m
__global__ void k0_init(float* __restrict__ out, int out_size) {
    int i = blockIdx.x * blockDim.x + threadIdx.x;
    int half = out_size >> 1;
    if (i < half) {
        out[i] = -1.0f;                   // grid_keypoints padding
    } else if (i < out_size) {
        out[i] = -4.5f;                   // upscale(-1) = 8*(-1)+3.5
    } else if (i < out_size + NPIX) {
        g_m[i - out_size] = 0u;           // relu max starts at 0
    }
}

// K1: depthwise (channel) max of relu(x), chunked over channels, atomicMax merge
__global__ void __launch_bounds__(256) k1_dwmax(const float* __restrict__ x) {
    int p = blockIdx.x * blockDim.x + threadIdx.x;   // pixel index in [0, NPIX)
    if (p >= NPIX) return;
    int chunk = blockIdx.y;
    int b  = p / HWn;
    int hw = p - b * HWn;
    const float* base = x + (size_t)b * CHWn + (size_t)chunk * K1_CHUNK * HWn + hw;
    float mx = 0.0f;   // relu floor
    #pragma unroll 8
    for (int i = 0; i < K1_CHUNK; i++) {
        mx = fmaxf(mx, base[(size_t)i * HWn]);
    }
    atomicMax(&g_m[p], __float_as_uint(mx));
}

// per-element predicate: relu(v)==m (depthwise max) AND >= all 3x3 neighbors
__device__ __forceinline__ int detect(const float* __restrict__ x,
                                      float vraw, int b, int c, int h, int w) {
    float v = fmaxf(vraw, 0.0f);
    float m = __uint_as_float(g_m[b * HWn + h * Wn + w]);
    if (v != m) return 0;
    const float* plane = x + (size_t)b * CHWn + (size_t)c * HWn;
    #pragma unroll
    for (int dh = -1; dh <= 1; dh++) {
        int nh = h + dh;
        if (nh < 0 || nh >= Hn) continue;
        #pragma unroll
        for (int dw = -1; dw <= 1; dw++) {
            if (dh == 0 && dw == 0) continue;
            int nw = w + dw;
            if (nw < 0 || nw >= Wn) continue;
            // v >= relu(n) <=> v >= n, since v >= 0
            if (v < plane[nh * Wn + nw]) return 0;
        }
    }
    return 1;
}

// K2: predicate over all elements (float4), block-ordered compaction into scratch
__global__ void __launch_bounds__(K2_TPB) k2_pred(const float* __restrict__ x) {
    int blk = blockIdx.x;
    int t = threadIdx.x;
    int e0 = blk * K2_EPB + t * 4;   // element index (fits in int: 52.4M < 2^31)

    // decode (b,c,h,w0); a float4 never crosses a row (W%4==0) nor a plane (HW%4==0)
    int b  = e0 / CHWn;
    int r  = e0 - b * CHWn;
    int c  = r / HWn;
    int hw = r - c * HWn;
    int h  = hw / Wn;
    int w0 = hw - h * Wn;

    float4 v4 = *reinterpret_cast<const float4*>(x + e0);

    int p0 = detect(x, v4.x, b, c, h, w0 + 0);
    int p1 = detect(x, v4.y, b, c, h, w0 + 1);
    int p2 = detect(x, v4.z, b, c, h, w0 + 2);
    int p3 = detect(x, v4.w, b, c, h, w0 + 3);
    int cnt = p0 + p1 + p2 + p3;

    // block inclusive scan (Hillis-Steele) over per-thread counts
    __shared__ int s[K2_TPB];
    s[t] = cnt;
    __syncthreads();
    #pragma unroll
    for (int off = 1; off < K2_TPB; off <<= 1) {
        int v = (t >= off) ? s[t - off] : 0;
        __syncthreads();
        s[t] += v;
        __syncthreads();
    }
    int excl = s[t] - cnt;
    int total = s[K2_TPB - 1];

    unsigned int* dst = g_scratch + (size_t)blk * CAP;
    int o = excl;
    if (p0) { if (o < CAP) dst[o] = (unsigned)((h << 8) | (w0 + 0)); o++; }
    if (p1) { if (o < CAP) dst[o] = (unsigned)((h << 8) | (w0 + 1)); o++; }
    if (p2) { if (o < CAP) dst[o] = (unsigned)((h << 8) | (w0 + 2)); o++; }
    if (p3) { if (o < CAP) dst[o] = (unsigned)((h << 8) | (w0 + 3)); o++; }

    if (t == 0) g_counts[blk] = (unsigned)min(total, CAP);
}

// K3: exclusive scan of 51200 block counts, single block of 1024 threads x 50 items
__global__ void __launch_bounds__(1024) k3_scan() {
    __shared__ unsigned int s[1024];
    int t = threadIdx.x;
    int base = t * (NBLK2 / 1024);   // 50 each
    const int ITEMS = NBLK2 / 1024;
    unsigned int sum = 0;
    for (int i = 0; i < ITEMS; i++) sum += g_counts[base + i];
    s[t] = sum;
    __syncthreads();
    for (int off = 1; off < 1024; off <<= 1) {
        unsigned int v = (t >= off) ? s[t - off] : 0u;
        __syncthreads();
        s[t] += v;
        __syncthreads();
    }
    unsigned int run = s[t] - sum;   // exclusive prefix for this thread's range
    for (int i = 0; i < ITEMS; i++) {
        g_offsets[base + i] = run;
        run += g_counts[base + i];
    }
}

// K4: scatter scratch records to final output
__global__ void __launch_bounds__(CAP) k4_scatter(float* __restrict__ out, int nmax) {
    int blk = blockIdx.x;
    unsigned int cnt = g_counts[blk];
    int t = threadIdx.x;
    if (t < (int)cnt) {
        unsigned int n = g_offsets[blk] + t;
        if (n < (unsigned)nmax) {
            unsigned int pk = g_scratch[(size_t)blk * CAP + t];
            float h = (float)(pk >> 8);
            float w = (float)(pk & 0xFF);
            out[2u * n + 0u] = h;
            out[2u * n + 1u] = w;
            float* kp = out + 2u * (unsigned)nmax;
            kp[2u * n + 0u] = 8.0f * h + 3.5f;   // upscale x3: ((p*2+.5)*2+.5)*2+.5
            kp[2u * n + 1u] = 8.0f * w + 3.5f;
        }
    }
}

extern "C" void kernel_launch(void* const* d_in, const int* in_sizes, int n_in,
                              void* d_out, int out_size) {
    const float* x = (const float*)d_in[0];
    float* out = (float*)d_out;
    int nmax = out_size / 4;   // [nmax,2] grid ints-as-floats + [nmax,2] keypoints

    // K0: init padding + zero g_m
    {
        int n = out_size + NPIX;
        k0_init<<<(n + 255) / 256, 256>>>(out, out_size);
    }
    // K1: depthwise max
    {
        dim3 grid((NPIX + 255) / 256, K1_NCHUNK);
        k1_dwmax<<<grid, 256>>>(x);
    }
    // K2: predicate + block compaction
    k2_pred<<<NBLK2, K2_TPB>>>(x);
    // K3: scan block counts
    k3_scan<<<1, 1024>>>();
    // K4: scatter
    k4_scatter<<<NBLK2, CAP>>>(out, nmax);
}

// round 3
// speedup vs baseline: 1.7181x; 1.7181x over previous
#include <cuda_runtime.h>

// Problem constants
#define Bn 16
#define Cn 512
#define Hn 80
#define Wn 80
#define HWn (Hn*Wn)          // 6400
#define CHWn (Cn*HWn)        // 3276800
#define TOTALn (Bn*CHWn)     // 52428800
#define NPIX (Bn*HWn)        // 102400
#define NPIX4 (NPIX/4)       // 25600

// K1: 4 pixels/thread (float4), 64 channels per chunk, 8 chunks
#define K1_CHUNK 64
#define K1_NCHUNK (Cn/K1_CHUNK)

// K2: 256 threads x 16 contiguous elements = 4096 elements per block
#define K2_TPB 256
#define K2_EPT 16
#define K2_EPB (K2_TPB*K2_EPT)     // 4096
#define NBLK2 (TOTALn/K2_EPB)      // 12800
#define CAP 64                     // max detections kept per K2 block (avg ~0.9)

// K3: scan 12800 counts with one block: 800 active threads x 16 counts
#define K3_TPB 1024
#define K3_ACTIVE 800
#define K3_ITEMS 16

// ---- scratch (allocation-free: __device__ globals) ----
__device__ unsigned int g_m[NPIX];               // per-pixel max of relu(x), as uint bits
__device__ unsigned int g_counts[NBLK2];
__device__ unsigned int g_offsets[NBLK2];
__device__ unsigned int g_scratch[NBLK2 * CAP];  // packed (h<<8)|w, block-ordered

// ---------------------------------------------------------------------------
// K0: init output padding and zero g_m
__global__ void k0_init(float* __restrict__ out, int out_size) {
    int i = blockIdx.x * blockDim.x + threadIdx.x;
    int half = out_size >> 1;
    if (i < half) {
        out[i] = -1.0f;                    // grid_keypoints padding
    } else if (i < out_size) {
        out[i] = -4.5f;                    // upscale(-1) = 8*(-1)+3.5
    } else if (i < out_size + NPIX) {
        g_m[i - out_size] = 0u;            // relu max floor
    }
}

// ---------------------------------------------------------------------------
// K1: per-pixel depthwise max of relu(x); float4 over 4 pixels, chunked channels,
// merged via u32 atomicMax on float bits (valid: relu >= 0). (R1-proven semantics.)
__global__ void __launch_bounds__(256) k1_dwmax(const float* __restrict__ x) {
    int p4 = blockIdx.x * blockDim.x + threadIdx.x;
    if (p4 >= NPIX4) return;
    int chunk = blockIdx.y;
    int p  = p4 * 4;
    int b  = p / HWn;
    int hw = p - b * HWn;
    const float* base = x + (size_t)b * CHWn + (size_t)chunk * K1_CHUNK * HWn + hw;

    float m0 = 0.f, m1 = 0.f, m2 = 0.f, m3 = 0.f;
    #pragma unroll 8
    for (int i = 0; i < K1_CHUNK; i++) {
        float4 v = *reinterpret_cast<const float4*>(base + (size_t)i * HWn);
        m0 = fmaxf(m0, v.x);
        m1 = fmaxf(m1, v.y);
        m2 = fmaxf(m2, v.z);
        m3 = fmaxf(m3, v.w);
    }
    atomicMax(&g_m[p+0], __float_as_uint(m0));
    atomicMax(&g_m[p+1], __float_as_uint(m1));
    atomicMax(&g_m[p+2], __float_as_uint(m2));
    atomicMax(&g_m[p+3], __float_as_uint(m3));
}

// ---------------------------------------------------------------------------
// neighbor test: v (= relu center = depthwise max) >= all in-bounds 3x3 raw
// neighbors (v>=0 makes v>=relu(n) <=> v>=n). Rare path.
__device__ __noinline__ bool neigh_ok(const float* __restrict__ plane,
                                      float v, int h, int w) {
    #pragma unroll
    for (int dh = -1; dh <= 1; dh++) {
        int nh = h + dh;
        if (nh < 0 || nh >= Hn) continue;
        #pragma unroll
        for (int dw = -1; dw <= 1; dw++) {
            if (dh == 0 && dw == 0) continue;
            int nw = w + dw;
            if (nw < 0 || nw >= Wn) continue;
            if (v < plane[nh * Wn + nw]) return false;
        }
    }
    return true;
}

// ---------------------------------------------------------------------------
// K2: per-element predicate over the full tensor, 16 contiguous elements/thread,
// ordered per-block compaction into scratch. (R1-proven structure, 4x bigger blocks.)
__global__ void __launch_bounds__(K2_TPB) k2_pred(const float* __restrict__ x) {
    int blk = blockIdx.x;
    int t = threadIdx.x;
    int e0 = blk * K2_EPB + t * K2_EPT;   // 16-aligned; within one (b,c,h) row

    int b  = e0 / CHWn;
    int r  = e0 - b * CHWn;
    int c  = r / HWn;
    int hw = r - c * HWn;
    int h  = hw / Wn;
    int w0 = hw - h * Wn;                 // multiple of 16

    const float* px = x + e0;
    const unsigned int* pm = &g_m[b * HWn + h * Wn + w0];
    const float* plane = x + (size_t)b * CHWn + (size_t)c * HWn;

    unsigned int det = 0;
    #pragma unroll
    for (int g = 0; g < 4; g++) {
        float4 xv = reinterpret_cast<const float4*>(px)[g];
        uint4  mu = reinterpret_cast<const uint4*>(pm)[g];
        float v0 = fmaxf(xv.x, 0.f), v1 = fmaxf(xv.y, 0.f);
        float v2 = fmaxf(xv.z, 0.f), v3 = fmaxf(xv.w, 0.f);
        if (__float_as_uint(v0) == mu.x && neigh_ok(plane, v0, h, w0 + 4*g + 0)) det |= 1u << (4*g + 0);
        if (__float_as_uint(v1) == mu.y && neigh_ok(plane, v1, h, w0 + 4*g + 1)) det |= 1u << (4*g + 1);
        if (__float_as_uint(v2) == mu.z && neigh_ok(plane, v2, h, w0 + 4*g + 2)) det |= 1u << (4*g + 2);
        if (__float_as_uint(v3) == mu.w && neigh_ok(plane, v3, h, w0 + 4*g + 3)) det |= 1u << (4*g + 3);
    }
    int cnt = __popc(det);

    // block inclusive scan (Hillis-Steele) over per-thread counts
    __shared__ int s[K2_TPB];
    s[t] = cnt;
    __syncthreads();
    #pragma unroll
    for (int off = 1; off < K2_TPB; off <<= 1) {
        int v = (t >= off) ? s[t - off] : 0;
        __syncthreads();
        s[t] += v;
        __syncthreads();
    }
    int o = s[t] - cnt;                  // exclusive offset
    int total = s[K2_TPB - 1];

    unsigned int* dst = g_scratch + (size_t)blk * CAP;
    unsigned int dd = det;
    while (dd) {
        int i = __ffs(dd) - 1;
        dd &= dd - 1;
        if (o < CAP) dst[o] = (unsigned)((h << 8) | (w0 + i));
        o++;
    }
    if (t == 0) g_counts[blk] = (unsigned)min(total, CAP);
}

// ---------------------------------------------------------------------------
// K3: exclusive scan of 12800 block counts; one block, 800 active threads x 16.
__global__ void __launch_bounds__(K3_TPB) k3_scan() {
    __shared__ unsigned int s[K3_TPB];
    int t = threadIdx.x;
    unsigned int loc[K3_ITEMS];
    unsigned int sum = 0;
    if (t < K3_ACTIVE) {
        const uint4* p = reinterpret_cast<const uint4*>(&g_counts[t * K3_ITEMS]);
        #pragma unroll
        for (int i = 0; i < K3_ITEMS / 4; i++) {
            uint4 v = p[i];
            loc[i*4+0] = v.x; loc[i*4+1] = v.y; loc[i*4+2] = v.z; loc[i*4+3] = v.w;
            sum += v.x + v.y + v.z + v.w;
        }
    }
    s[t] = sum;
    __syncthreads();
    #pragma unroll
    for (int off = 1; off < K3_TPB; off <<= 1) {
        unsigned int v = (t >= off) ? s[t - off] : 0u;
        __syncthreads();
        s[t] += v;
        __syncthreads();
    }
    if (t < K3_ACTIVE) {
        unsigned int run = s[t] - sum;   // exclusive prefix of this thread's range
        #pragma unroll
        for (int i = 0; i < K3_ITEMS; i++) {
            g_offsets[t * K3_ITEMS + i] = run;
            run += loc[i];
        }
    }
}

// ---------------------------------------------------------------------------
// K4: scatter scratch records to final output.
__global__ void __launch_bounds__(CAP) k4_scatter(float* __restrict__ out, int nmax) {
    int blk = blockIdx.x;
    unsigned int cnt = g_counts[blk];
    int t = threadIdx.x;
    if (t < (int)cnt) {
        unsigned int n = g_offsets[blk] + (unsigned)t;
        if (n < (unsigned)nmax) {
            unsigned int pk = g_scratch[(size_t)blk * CAP + t];
            float h = (float)(pk >> 8);
            float w = (float)(pk & 0xFF);
            out[2u*n + 0u] = h;
            out[2u*n + 1u] = w;
            float* kp = out + 2u * (unsigned)nmax;
            kp[2u*n + 0u] = 8.0f * h + 3.5f;   // ((p*2+.5)*2+.5)*2+.5
            kp[2u*n + 1u] = 8.0f * w + 3.5f;
        }
    }
}

// ---------------------------------------------------------------------------
extern "C" void kernel_launch(void* const* d_in, const int* in_sizes, int n_in,
                              void* d_out, int out_size) {
    const float* x = (const float*)d_in[0];
    float* out = (float*)d_out;
    int nmax = out_size / 4;

    {   // K0: padding + zero g_m
        int n = out_size + NPIX;
        k0_init<<<(n + 255) / 256, 256>>>(out, out_size);
    }
    {   // K1: depthwise relu-max
        dim3 grid((NPIX4 + 255) / 256, K1_NCHUNK);
        k1_dwmax<<<grid, 256>>>(x);
    }
    k2_pred<<<NBLK2, K2_TPB>>>(x);   // predicate + ordered block compaction
    k3_scan<<<1, K3_TPB>>>();        // scan 12800 counts
    k4_scatter<<<NBLK2, CAP>>>(out, nmax);
}

// round 4
// speedup vs baseline: 1.8011x; 1.0483x over previous
#include <cuda_runtime.h>

// Problem constants
#define Bn 16
#define Cn 512
#define Hn 80
#define Wn 80
#define HWn (Hn*Wn)          // 6400
#define CHWn (Cn*HWn)        // 3276800
#define TOTALn (Bn*CHWn)     // 52428800
#define NPIX (Bn*HWn)        // 102400

// K2: 256 threads x 16 contiguous elements = 4096 elements per block
#define K2_TPB 256
#define K2_EPT 16
#define K2_EPB (K2_TPB*K2_EPT)     // 4096
#define NBLK2 (TOTALn/K2_EPB)      // 12800
#define CAP 64                     // max detections per K2 block (avg ~8, Poisson)

// K3: scan 12800 counts, one block, 800 active threads x 16 counts
#define K3_TPB 1024
#define K3_ACTIVE 800
#define K3_ITEMS 16

// ---- scratch (allocation-free: __device__ globals) ----
__device__ unsigned int   g_m[NPIX];              // per-pixel max of relu(x), float bits
__device__ unsigned short g_m16[NPIX];            // top 16 bits of g_m (prefilter)
__device__ unsigned int   g_counts[NBLK2];
__device__ unsigned int   g_offsets[NBLK2];
__device__ unsigned int   g_scratch[NBLK2 * CAP]; // packed (h<<8)|w, block-ordered

// ---------------------------------------------------------------------------
// K0: init output padding only (g_m needs no init: K1 writes every pixel)
__global__ void k0_init(float4* __restrict__ out4, int n4, int half4) {
    int i = blockIdx.x * blockDim.x + threadIdx.x;
    if (i < half4) {
        out4[i] = make_float4(-1.f, -1.f, -1.f, -1.f);       // grid padding
    } else if (i < n4) {
        out4[i] = make_float4(-4.5f, -4.5f, -4.5f, -4.5f);   // 8*(-1)+3.5
    }
}

// ---------------------------------------------------------------------------
// K1: per-pixel depthwise max of relu(x). One thread per pixel, all 512 channels,
// direct write (no atomics). Warp reads 32 consecutive floats = one 128B line.
__global__ void __launch_bounds__(256) k1_dwmax(const float* __restrict__ x) {
    int p = blockIdx.x * blockDim.x + threadIdx.x;
    if (p >= NPIX) return;
    int b  = p / HWn;
    int hw = p - b * HWn;
    const float* base = x + (size_t)b * CHWn + hw;
    float m = 0.0f;                       // relu floor
    #pragma unroll 16
    for (int c = 0; c < Cn; c++) {
        m = fmaxf(m, base[(size_t)c * HWn]);
    }
    unsigned int mb = __float_as_uint(m);
    g_m[p]   = mb;
    g_m16[p] = (unsigned short)(mb >> 16);
}

// ---------------------------------------------------------------------------
// neighbor test: v (>=0) must be >= all in-bounds raw 3x3 neighbors. Rare path.
__device__ __noinline__ bool neigh_ok(const float* __restrict__ plane,
                                      float v, int h, int w) {
    #pragma unroll
    for (int dh = -1; dh <= 1; dh++) {
        int nh = h + dh;
        if (nh < 0 || nh >= Hn) continue;
        #pragma unroll
        for (int dw = -1; dw <= 1; dw++) {
            if (dh == 0 && dw == 0) continue;
            int nw = w + dw;
            if (nw < 0 || nw >= Wn) continue;
            if (v < plane[nh * Wn + nw]) return false;
        }
    }
    return true;
}

// ---------------------------------------------------------------------------
// K2: per-element predicate, 16 contiguous elements/thread. 16-bit prefilter on
// g_m16, exact g_m check only on prefilter hit. Ordered per-block compaction.
__global__ void __launch_bounds__(K2_TPB) k2_pred(const float* __restrict__ x) {
    int blk = blockIdx.x;
    int t = threadIdx.x;
    int lane = t & 31;
    int warp = t >> 5;
    int e0 = blk * K2_EPB + t * K2_EPT;   // 16-aligned; within one (b,c,h) row

    int b  = e0 / CHWn;
    int r  = e0 - b * CHWn;
    int c  = r / HWn;
    int hw = r - c * HWn;
    int h  = hw / Wn;
    int w0 = hw - h * Wn;                 // multiple of 16

    const float* px = x + e0;
    int pix0 = b * HWn + h * Wn + w0;
    const unsigned short* pm16 = &g_m16[pix0];
    const float* plane = x + (size_t)b * CHWn + (size_t)c * HWn;

    unsigned int det = 0;
    #pragma unroll
    for (int g = 0; g < 2; g++) {
        // 8 elements per group: 2x float4 of x, 1x uint4 of g_m16 (8 u16)
        float4 xa = reinterpret_cast<const float4*>(px)[2*g + 0];
        float4 xb = reinterpret_cast<const float4*>(px)[2*g + 1];
        uint4  m16 = reinterpret_cast<const uint4*>(pm16)[g];
        float v[8];
        v[0] = fmaxf(xa.x, 0.f); v[1] = fmaxf(xa.y, 0.f);
        v[2] = fmaxf(xa.z, 0.f); v[3] = fmaxf(xa.w, 0.f);
        v[4] = fmaxf(xb.x, 0.f); v[5] = fmaxf(xb.y, 0.f);
        v[6] = fmaxf(xb.z, 0.f); v[7] = fmaxf(xb.w, 0.f);
        unsigned int mw[4] = {m16.x, m16.y, m16.z, m16.w};
        #pragma unroll
        for (int i = 0; i < 8; i++) {
            unsigned int t16 = (mw[i >> 1] >> ((i & 1) * 16)) & 0xFFFFu;
            if ((__float_as_uint(v[i]) >> 16) == t16) {
                int wi = w0 + 8*g + i;
                // exact check + neighbor check (rare)
                if (__float_as_uint(v[i]) == g_m[pix0 + 8*g + i] &&
                    neigh_ok(plane, v[i], h, wi)) {
                    det |= 1u << (8*g + i);
                }
            }
        }
    }
    int cnt = __popc(det);

    // block scan via warp shuffles (2 barriers)
    int incl = cnt;
    #pragma unroll
    for (int off = 1; off < 32; off <<= 1) {
        int n = __shfl_up_sync(0xFFFFFFFFu, incl, off);
        if (lane >= off) incl += n;
    }
    __shared__ int ws[K2_TPB / 32];
    __shared__ int s_total;
    if (lane == 31) ws[warp] = incl;
    __syncthreads();
    if (t < K2_TPB / 32) {                 // 8 lanes of warp 0
        int v = ws[t];
        int iv = v;
        #pragma unroll
        for (int off = 1; off < K2_TPB / 32; off <<= 1) {
            int n = __shfl_up_sync(0x000000FFu, iv, off);
            if (t >= off) iv += n;
        }
        ws[t] = iv - v;                    // exclusive warp base
        if (t == K2_TPB / 32 - 1) s_total = iv;
    }
    __syncthreads();

    int o = ws[warp] + (incl - cnt);
    unsigned int* dst = g_scratch + (size_t)blk * CAP;
    unsigned int dd = det;
    while (dd) {
        int i = __ffs(dd) - 1;
        dd &= dd - 1;
        if (o < CAP) dst[o] = (unsigned)((h << 8) | (w0 + i));
        o++;
    }
    if (t == 0) g_counts[blk] = (unsigned)min(s_total, CAP);
}

// ---------------------------------------------------------------------------
// K3: exclusive scan of 12800 block counts; warp-shuffle scan, 2 barriers.
__global__ void __launch_bounds__(K3_TPB) k3_scan() {
    int t = threadIdx.x;
    int lane = t & 31;
    int warp = t >> 5;
    unsigned int loc[K3_ITEMS];
    unsigned int sum = 0;
    if (t < K3_ACTIVE) {
        const uint4* p = reinterpret_cast<const uint4*>(&g_counts[t * K3_ITEMS]);
        #pragma unroll
        for (int i = 0; i < K3_ITEMS / 4; i++) {
            uint4 v = p[i];
            loc[i*4+0] = v.x; loc[i*4+1] = v.y; loc[i*4+2] = v.z; loc[i*4+3] = v.w;
            sum += v.x + v.y + v.z + v.w;
        }
    }
    unsigned int incl = sum;
    #pragma unroll
    for (int off = 1; off < 32; off <<= 1) {
        unsigned int n = __shfl_up_sync(0xFFFFFFFFu, incl, off);
        if (lane >= off) incl += n;
    }
    __shared__ unsigned int ws[K3_TPB / 32];    // 32 warps
    if (lane == 31) ws[warp] = incl;
    __syncthreads();
    if (t < K3_TPB / 32) {                      // warp 0 scans 32 warp sums
        unsigned int v = ws[t];
        unsigned int iv = v;
        #pragma unroll
        for (int off = 1; off < 32; off <<= 1) {
            unsigned int n = __shfl_up_sync(0xFFFFFFFFu, iv, off);
            if (t >= off) iv += n;
        }
        ws[t] = iv - v;                         // exclusive
    }
    __syncthreads();
    if (t < K3_ACTIVE) {
        unsigned int run = ws[warp] + (incl - sum);   // exclusive prefix
        #pragma unroll
        for (int i = 0; i < K3_ITEMS; i++) {
            g_offsets[t * K3_ITEMS + i] = run;
            run += loc[i];
        }
    }
}

// ---------------------------------------------------------------------------
// K4: scatter scratch records to final output.
__global__ void __launch_bounds__(CAP) k4_scatter(float* __restrict__ out, int nmax) {
    int blk = blockIdx.x;
    unsigned int cnt = g_counts[blk];
    int t = threadIdx.x;
    if (t < (int)cnt) {
        unsigned int n = g_offsets[blk] + (unsigned)t;
        if (n < (unsigned)nmax) {
            unsigned int pk = g_scratch[(size_t)blk * CAP + t];
            float h = (float)(pk >> 8);
            float w = (float)(pk & 0xFF);
            out[2u*n + 0u] = h;
            out[2u*n + 1u] = w;
            float* kp = out + 2u * (unsigned)nmax;
            kp[2u*n + 0u] = 8.0f * h + 3.5f;   // ((p*2+.5)*2+.5)*2+.5
            kp[2u*n + 1u] = 8.0f * w + 3.5f;
        }
    }
}

// ---------------------------------------------------------------------------
extern "C" void kernel_launch(void* const* d_in, const int* in_sizes, int n_in,
                              void* d_out, int out_size) {
    const float* x = (const float*)d_in[0];
    float* out = (float*)d_out;
    int nmax = out_size / 4;

    {   // K0: output padding (float4)
        int n4 = out_size / 4;
        int half4 = (out_size / 2) / 4;
        k0_init<<<(n4 + 255) / 256, 256>>>((float4*)out, n4, half4);
    }
    k1_dwmax<<<(NPIX + 255) / 256, 256>>>(x);   // 400 blocks, no atomics
    k2_pred<<<NBLK2, K2_TPB>>>(x);              // prefiltered predicate + compaction
    k3_scan<<<1, K3_TPB>>>();                   // warp-shuffle scan of 12800 counts
    k4_scatter<<<NBLK2, CAP>>>(out, nmax);
}